// round 11
// baseline (speedup 1.0000x reference)
#include <cuda_runtime.h>
#include <cuda_bf16.h>
#include <cstdint>

// ===========================================================================
// TransConvLayer reduction (validated R4/R6-R10):
//   out[n,:] = source[n,:] @ Wbar^T + bbar
// Round 11: single kernel (W head-fold inlined; prep launch + gap removed)
//   + TILE_M=256 with 8 warps (warp tile 64x32): B-fragment traffic
//   amortized over 2x rows -> 384 KB crossbar per 128 rows (was 512).
//   K chunked 4x64, smem ~80 KB -> 2 CTAs/SM retained.
// Math identical: D = Xhi*Whi + Xhi*Wlo + Xlo*Whi (fused bf16x3).
// ===========================================================================

#define IN_CH   256
#define OUT_CH  64
#define TILE_M  256
#define THREADS 256            // 8 warps: 4 row-groups x 2 col-groups
#define KCH     64             // K per chunk
#define NCH     4              // chunks

// SMEM layout (bytes from 1024-aligned base). Row stride 128 B (64 bf16).
#define OFF_WHI  0             // W chunk hi: 64 x 128 B = 8 KB
#define OFF_WLO  8192          // W chunk lo: 8 KB
#define OFF_XHI  16384         // X chunk hi: 256 x 128 B = 32 KB
#define OFF_XLO  49152         // X chunk lo: 32 KB
#define OFF_BIAS 81920         // 64 floats
#define SMEM_SZ  82176
#define SMEM_DYN (SMEM_SZ + 1024)

// ---- helpers ----------------------------------------------------------------

__device__ __forceinline__ uint32_t smem_u32(const void* p) {
    uint32_t a;
    asm("{ .reg .u64 t; cvta.to.shared.u64 t, %1; cvt.u32.u64 %0, t; }"
        : "=r"(a) : "l"(p));
    return a;
}

__device__ __forceinline__ void ldsm_x4(uint32_t* r, uint32_t addr) {
    asm volatile("ldmatrix.sync.aligned.m8n8.x4.shared.b16 {%0,%1,%2,%3}, [%4];"
                 : "=r"(r[0]), "=r"(r[1]), "=r"(r[2]), "=r"(r[3]) : "r"(addr));
}

__device__ __forceinline__ void mma_16816(float* c, const uint32_t* a,
                                          const uint32_t* b) {
    asm volatile(
        "mma.sync.aligned.m16n8k16.row.col.f32.bf16.bf16.f32 "
        "{%0,%1,%2,%3}, {%4,%5,%6,%7}, {%8,%9}, {%0,%1,%2,%3};"
        : "+f"(c[0]), "+f"(c[1]), "+f"(c[2]), "+f"(c[3])
        : "r"(a[0]), "r"(a[1]), "r"(a[2]), "r"(a[3]), "r"(b[0]), "r"(b[1]));
}

// split a float pair into packed bf16x2 hi / lo words
__device__ __forceinline__ void split_pair(float x, float y,
                                           uint32_t& h, uint32_t& l) {
    __nv_bfloat162 hh = __floats2bfloat162_rn(x, y);
    float2 hf = __bfloat1622float2(hh);
    __nv_bfloat162 ll = __floats2bfloat162_rn(x - hf.x, y - hf.y);
    h = *reinterpret_cast<const uint32_t*>(&hh);
    l = *reinterpret_cast<const uint32_t*>(&ll);
}

// fold 4 heads of Wv (fp32) -> wbar, split, return packed hi/lo for 4 floats
__device__ __forceinline__ void fold_split4(const float4& a0, const float4& a1,
                                            const float4& a2, const float4& a3,
                                            uint32_t& h0, uint32_t& h1,
                                            uint32_t& l0, uint32_t& l1) {
    // sequential add order matches the validated prep kernel exactly
    float w0 = 0.25f * (((a0.x + a1.x) + a2.x) + a3.x);
    float w1 = 0.25f * (((a0.y + a1.y) + a2.y) + a3.y);
    float w2 = 0.25f * (((a0.z + a1.z) + a2.z) + a3.z);
    float w3 = 0.25f * (((a0.w + a1.w) + a2.w) + a3.w);
    split_pair(w0, w1, h0, l0);
    split_pair(w2, w3, h1, l1);
}

// ---- single fused kernel ------------------------------------------------------

__global__ __launch_bounds__(THREADS, 2)
void gemm_kernel(const float* __restrict__ X,
                 const float* __restrict__ Wv_w,
                 const float* __restrict__ Wv_b,
                 float* __restrict__ Y, int N) {
    extern __shared__ char smem_raw[];
    uint32_t raw  = smem_u32(smem_raw);
    uint32_t base = (raw + 1023) & ~1023u;
    char*    sm   = smem_raw + (base - raw);

    const int tid  = threadIdx.x;
    const int wid  = tid >> 5;
    const int lid  = tid & 31;
    const int wr   = wid >> 1;            // 0..3  -> rows wr*64
    const int wc   = wid & 1;             // 0..1  -> cols wc*32
    const int row0 = blockIdx.x * TILE_M;

    // ---- per-lane ldmatrix address components (row stride 128 B) ----
    const int rA   = wr * 64 + ((lid >> 3) & 1) * 8 + (lid & 7);
    const int chA  = lid >> 4;
    const int swzA = rA & 7;
    uint32_t aRow[4];
    #pragma unroll
    for (int mt = 0; mt < 4; ++mt) aRow[mt] = (uint32_t)((rA + mt * 16) * 128);

    const int rBb  = wc * 32 + ((lid >> 4) & 1) * 8 + (lid & 7);
    const int chB  = (lid >> 3) & 1;
    const int swzB = rBb & 7;
    const uint32_t bRow0 = (uint32_t)(rBb * 128);
    const uint32_t bRow1 = (uint32_t)((rBb + 16) * 128);

    const uint32_t whi = base + OFF_WHI;
    const uint32_t wlo = base + OFF_WLO;
    const uint32_t xhi = base + OFF_XHI;
    const uint32_t xlo = base + OFF_XLO;

    float acc[4][4][4];
    #pragma unroll
    for (int mt = 0; mt < 4; ++mt)
        #pragma unroll
        for (int nt = 0; nt < 4; ++nt)
            #pragma unroll
            for (int q = 0; q < 4; ++q) acc[mt][nt][q] = 0.f;

    #pragma unroll 1
    for (int kc = 0; kc < NCH; ++kc) {
        const int kc0 = kc * KCH;

        // ---- stage W chunk: fold 4 heads from Wv_w, split, swizzled STS ----
        // 64 rows x 8 chunks of 16B = 512 tasks, 2 per thread
        #pragma unroll
        for (int it = 0; it < 2; ++it) {
            int idx = it * THREADS + tid;     // 0..511
            int r   = idx >> 3;               // d row 0..63
            int c   = idx & 7;                // 16B bf16 chunk = 8 k values
            const float* wp = Wv_w + (size_t)r * IN_CH + kc0 + c * 8;
            float4 h0a = *reinterpret_cast<const float4*>(wp);
            float4 h0b = *reinterpret_cast<const float4*>(wp + 4);
            float4 h1a = *reinterpret_cast<const float4*>(wp + 64 * IN_CH);
            float4 h1b = *reinterpret_cast<const float4*>(wp + 64 * IN_CH + 4);
            float4 h2a = *reinterpret_cast<const float4*>(wp + 128 * IN_CH);
            float4 h2b = *reinterpret_cast<const float4*>(wp + 128 * IN_CH + 4);
            float4 h3a = *reinterpret_cast<const float4*>(wp + 192 * IN_CH);
            float4 h3b = *reinterpret_cast<const float4*>(wp + 192 * IN_CH + 4);
            uint4 h, l;
            fold_split4(h0a, h1a, h2a, h3a, h.x, h.y, l.x, l.y);
            fold_split4(h0b, h1b, h2b, h3b, h.z, h.w, l.z, l.w);
            uint32_t off = (uint32_t)(r * 128 + ((c ^ (r & 7)) << 4));
            *reinterpret_cast<uint4*>(sm + OFF_WHI + off) = h;
            *reinterpret_cast<uint4*>(sm + OFF_WLO + off) = l;
        }

        // bias fold (once)
        if (kc == 0 && tid < OUT_CH) {
            float s = (((Wv_b[tid] + Wv_b[64 + tid]) + Wv_b[128 + tid])
                       + Wv_b[192 + tid]);
            *reinterpret_cast<float*>(sm + OFF_BIAS + tid * 4) = 0.25f * s;
        }

        // ---- stage X chunk: fp32 -> bf16 hi/lo, swizzled STS ----
        // 256 rows x 8 chunks = 2048 tasks, 8 per thread
        #pragma unroll
        for (int it = 0; it < 8; ++it) {
            int idx = it * THREADS + tid;     // 0..2047
            int r   = idx >> 3;               // 0..255
            int c   = idx & 7;
            int gr  = row0 + r;
            if (gr >= N) gr = N - 1;          // clamp; epilogue guards rows
            const float4* gp = reinterpret_cast<const float4*>(
                X + (size_t)gr * IN_CH + kc0 + c * 8);
            float4 a = gp[0];
            float4 b = gp[1];
            uint4 h, l;
            split_pair(a.x, a.y, h.x, l.x);
            split_pair(a.z, a.w, h.y, l.y);
            split_pair(b.x, b.y, h.z, l.z);
            split_pair(b.z, b.w, h.w, l.w);
            uint32_t off = (uint32_t)(r * 128 + ((c ^ (r & 7)) << 4));
            *reinterpret_cast<uint4*>(sm + OFF_XHI + off) = h;
            *reinterpret_cast<uint4*>(sm + OFF_XLO + off) = l;
        }
        __syncthreads();

        // ---- fused 3-term MMA over this chunk: 4 k-steps ----
        #pragma unroll
        for (int ks = 0; ks < 4; ++ks) {
            const uint32_t oA = (uint32_t)(((2 * ks + chA) ^ swzA) << 4);
            const uint32_t oB = (uint32_t)(((2 * ks + chB) ^ swzB) << 4);

            uint32_t ah[4][4];
            #pragma unroll
            for (int mt = 0; mt < 4; ++mt)
                ldsm_x4(ah[mt], xhi + aRow[mt] + oA);
            uint32_t bh[8];
            ldsm_x4(bh,     whi + bRow0 + oB);
            ldsm_x4(bh + 4, whi + bRow1 + oB);

            // term 1: Xhi * Whi
            #pragma unroll
            for (int mt = 0; mt < 4; ++mt)
                #pragma unroll
                for (int nt = 0; nt < 4; ++nt)
                    mma_16816(acc[mt][nt], ah[mt], bh + 2 * nt);

            // term 2: Xhi * Wlo (reuse ah; ah dies after)
            {
                uint32_t bl[8];
                ldsm_x4(bl,     wlo + bRow0 + oB);
                ldsm_x4(bl + 4, wlo + bRow1 + oB);
                #pragma unroll
                for (int mt = 0; mt < 4; ++mt)
                    #pragma unroll
                    for (int nt = 0; nt < 4; ++nt)
                        mma_16816(acc[mt][nt], ah[mt], bl + 2 * nt);
            }
            // term 3: Xlo * Whi (reuse bh)
            {
                uint32_t al[4][4];
                #pragma unroll
                for (int mt = 0; mt < 4; ++mt)
                    ldsm_x4(al[mt], xlo + aRow[mt] + oA);
                #pragma unroll
                for (int mt = 0; mt < 4; ++mt)
                    #pragma unroll
                    for (int nt = 0; nt < 4; ++nt)
                        mma_16816(acc[mt][nt], al[mt], bh + 2 * nt);
            }
        }
        __syncthreads();   // before buffers are overwritten by next chunk
    }

    // ---- epilogue: D frag -> global, + bias (from smem) ----
    const int qr = lid >> 2;               // 0..7
    const int qc = (lid & 3) * 2;
    const float* bias = reinterpret_cast<const float*>(sm + OFF_BIAS);
    #pragma unroll
    for (int mt = 0; mt < 4; ++mt) {
        int r_lo = row0 + wr * 64 + mt * 16 + qr;
        #pragma unroll
        for (int nt = 0; nt < 4; ++nt) {
            int col = wc * 32 + nt * 8 + qc;
            float b0 = bias[col], b1 = bias[col + 1];
            if (r_lo < N) {
                float2 v = make_float2(acc[mt][nt][0] + b0,
                                       acc[mt][nt][1] + b1);
                *reinterpret_cast<float2*>(Y + (size_t)r_lo * OUT_CH + col) = v;
            }
            if (r_lo + 8 < N) {
                float2 v = make_float2(acc[mt][nt][2] + b0,
                                       acc[mt][nt][3] + b1);
                *reinterpret_cast<float2*>(Y + (size_t)(r_lo + 8) * OUT_CH + col) = v;
            }
        }
    }
}

// ---------------------------------------------------------------------------

extern "C" void kernel_launch(void* const* d_in, const int* in_sizes, int n_in,
                              void* d_out, int out_size) {
    // inputs: query_input, source_input, Wq_w, Wq_b, Wk_w, Wk_b, Wv_w, Wv_b
    const float* src  = (const float*)d_in[1];
    const float* Wv_w = (const float*)d_in[6];
    const float* Wv_b = (const float*)d_in[7];
    float* out = (float*)d_out;
    const int N = in_sizes[1] / IN_CH;

    cudaFuncSetAttribute(gemm_kernel,
                         cudaFuncAttributeMaxDynamicSharedMemorySize, SMEM_DYN);

    const int grid = (N + TILE_M - 1) / TILE_M;   // 391
    gemm_kernel<<<grid, THREADS, SMEM_DYN>>>(src, Wv_w, Wv_b, out, N);
}